// round 3
// baseline (speedup 1.0000x reference)
#include <cuda_runtime.h>
#include <math_constants.h>

// ---------------------------------------------------------------------------
// Warp-cooperative 32-ary lower_bound over a sorted array.
// Returns first index i with s[i] >= target (may be n).
// ~4 dependent probe rounds for n = 1M. All 32 lanes of the calling warp
// must participate.
// ---------------------------------------------------------------------------
template <typename T>
__device__ __forceinline__ int warp_lower_bound(const T* __restrict__ s, int n,
                                                int target, int lane) {
    int lo = 0, hi = n;  // invariant: answer in [lo, hi]
    while (hi - lo > 31) {
        const int range = hi - lo;
        const int step  = (range + 31) >> 5;  // ceil(range/32)
        const int idx   = lo + lane * step;
        bool lt = false;
        if (idx < hi) lt = ((int)s[idx] < target);
        const unsigned mask = __ballot_sync(0xffffffffu, lt);
        const int cnt = __popc(mask);  // prefix of lanes with s[idx] < target
        if (cnt == 0) { hi = lo; break; }  // s[lo] >= target -> answer == lo
        const int new_lo = lo + (cnt - 1) * step + 1;
        const int new_hi = min(lo + cnt * step, hi);
        lo = new_lo; hi = new_hi;
    }
    // hi - lo <= 31: lane 31 is always padding (ge=true), so mask != 0
    const int idx = lo + lane;
    const bool ge = (idx < hi) ? ((int)s[idx] >= target) : true;
    const unsigned mask = __ballot_sync(0xffffffffu, ge);
    return lo + (__ffs(mask) - 1);
}

// ---------------------------------------------------------------------------
// Fused kernel: one block per segment. Warps 0/1 first locate the segment's
// row range via cooperative binary search on the sorted segment_ids (no
// separate offsets kernel, no extra launch). Then 128 threads = 4 row-groups
// x 32 lanes stream the segment: lane l owns features [4l, 4l+4) via float4
// (coalesced LDG.128, streaming cache hint). Cross-group combine in shared
// memory; thread f writes the 4 stats for feature f.
// Handles both int64 (reference dtype) and int32 (JAX default) segment_ids
// via an on-device dtype sniff.
// ---------------------------------------------------------------------------
__global__ void __launch_bounds__(128, 12)
seg_pool_kernel(const float* __restrict__ x, const void* __restrict__ seg,
                float* __restrict__ out, int n, int G) {
    const int g    = blockIdx.x;
    const int lane = threadIdx.x & 31;
    const int grp  = threadIdx.x >> 5;

    __shared__ int sbounds[2];

    if (grp < 2) {
        // dtype sniff: int64 word at index n/4 covers int32 elements n/2,
        // n/2+1. Sorted ids: middle element ~G/2 != 0, so int32 data read as
        // int64 is >= 2^32; genuine int64 data stays a small id.
        const long long probe = ((const long long*)seg)[n >> 2];
        const bool is64 = (probe >= 0) && (probe < (1LL << 31));
        const int target = g + grp;  // warp0: lb(g)=start, warp1: lb(g+1)=end
        int b;
        if (is64) b = warp_lower_bound((const long long*)seg, n, target, lane);
        else      b = warp_lower_bound((const int*)seg,       n, target, lane);
        if (lane == 0) sbounds[grp] = b;
    }
    __syncthreads();

    const int start = sbounds[0];
    const int end   = sbounds[1];

    float4 s  = make_float4(0.f, 0.f, 0.f, 0.f);
    float4 q  = make_float4(0.f, 0.f, 0.f, 0.f);
    float4 mx = make_float4(-CUDART_INF_F, -CUDART_INF_F, -CUDART_INF_F, -CUDART_INF_F);
    float4 mn = make_float4( CUDART_INF_F,  CUDART_INF_F,  CUDART_INF_F,  CUDART_INF_F);

    const float4* __restrict__ xv = (const float4*)x;  // row stride = 32 float4

    #pragma unroll 4
    for (int r = start + grp; r < end; r += 4) {
        float4 v = __ldcs(&xv[(size_t)r * 32 + lane]);
        s.x += v.x; s.y += v.y; s.z += v.z; s.w += v.w;
        q.x = fmaf(v.x, v.x, q.x); q.y = fmaf(v.y, v.y, q.y);
        q.z = fmaf(v.z, v.z, q.z); q.w = fmaf(v.w, v.w, q.w);
        mx.x = fmaxf(mx.x, v.x); mx.y = fmaxf(mx.y, v.y);
        mx.z = fmaxf(mx.z, v.z); mx.w = fmaxf(mx.w, v.w);
        mn.x = fminf(mn.x, v.x); mn.y = fminf(mn.y, v.y);
        mn.z = fminf(mn.z, v.z); mn.w = fminf(mn.w, v.w);
    }

    // partials: [stat][group][lane] as float4 -> 4*4*32*16B = 8 KB
    __shared__ float4 sm4[4][4][32];
    sm4[0][grp][lane] = s;
    sm4[1][grp][lane] = q;
    sm4[2][grp][lane] = mx;
    sm4[3][grp][lane] = mn;
    __syncthreads();

    // thread f in [0,128) combines the 4 group partials for feature f
    const int f = threadIdx.x;
    float sum = 0.f, sq = 0.f;
    float M = -CUDART_INF_F, m = CUDART_INF_F;
    #pragma unroll
    for (int k = 0; k < 4; k++) {
        const float* p0 = (const float*)&sm4[0][k][0];
        const float* p1 = (const float*)&sm4[1][k][0];
        const float* p2 = (const float*)&sm4[2][k][0];
        const float* p3 = (const float*)&sm4[3][k][0];
        sum += p0[f];
        sq  += p1[f];
        M = fmaxf(M, p2[f]);
        m = fminf(m, p3[f]);
    }

    const float cnt  = (float)(end - start);
    const float mean = sum / cnt;
    const float var  = (sq - cnt * mean * mean) / (cnt - 1.0f);
    const float sd   = sqrtf(fmaxf(var, 0.0f));

    float* o = out + (size_t)g * 512;  // [4][128] per segment
    o[f]        = M;
    o[128 + f]  = m;
    o[256 + f]  = mean;
    o[384 + f]  = sd;
}

extern "C" void kernel_launch(void* const* d_in, const int* in_sizes, int n_in,
                              void* d_out, int out_size) {
    const float* x   = (const float*)d_in[0];
    const void*  seg = d_in[1];
    float* out = (float*)d_out;

    const int D = 128;
    const int n = in_sizes[0] / D;          // number of rows
    const int G = out_size / (4 * D);       // number of segments

    seg_pool_kernel<<<G, 128>>>(x, seg, out, n, G);
}

// round 4
// speedup vs baseline: 1.1081x; 1.1081x over previous
#include <cuda_runtime.h>
#include <math_constants.h>

// Scratch for segment offsets (allocation-free rule: __device__ global).
__device__ int g_offsets[65537];

// ---------------------------------------------------------------------------
// Kernel 1: streaming boundary scan over the SORTED segment_ids array.
// One coalesced load per element; the successor id comes from the lane to the
// right via shfl (lane 31 issues one extra scalar load). At each transition
// id -> next, the thread fills g_offsets for every segment in (id, next].
// Thread 0 fills the head [0, s[0]]; the last element fills the tail up to G.
// Handles int64 (reference dtype) and int32 (JAX default) via a sniff.
// ---------------------------------------------------------------------------
__global__ void seg_boundaries_kernel(const void* __restrict__ seg, int n, int G) {
    const int i    = blockIdx.x * blockDim.x + threadIdx.x;
    const int lane = threadIdx.x & 31;

    // dtype sniff (warp-uniform): int64 word at index n/4 covers int32
    // elements n/2, n/2+1. Sorted ids: middle element ~G/2 != 0, so int32
    // data read as int64 is >= 2^32; genuine int64 data stays a small id.
    const long long probe = ((const long long*)seg)[n >> 2];
    const bool is64 = (probe >= 0) && (probe < (1LL << 31));

    const bool valid = (i < n);
    int id = 0;
    if (valid) {
        id = is64 ? (int)((const long long*)seg)[i] : ((const int*)seg)[i];
    }

    // successor: from right neighbor lane, else one scalar load / sentinel G
    const int from_shfl = __shfl_down_sync(0xffffffffu, id, 1);
    int next = G;
    if (valid) {
        if (i + 1 < n) {
            if (lane < 31) next = from_shfl;
            else next = is64 ? (int)((const long long*)seg)[i + 1]
                             : ((const int*)seg)[i + 1];
        }
    }

    if (!valid) return;

    if (i == 0) {
        for (int g = 0; g <= id; g++) g_offsets[g] = 0;
    }
    // first row of every segment in (id, next] is i+1  (no-op when id==next)
    for (int g = id + 1; g <= next; g++) g_offsets[g] = i + 1;
}

// ---------------------------------------------------------------------------
// Kernel 2 (identical to the measured-best R2 version): one block per
// segment. 128 threads = 4 row-groups x 32 lanes. Lane l owns features
// [4l, 4l+4) via float4 (coalesced LDG.128, streaming hint). Row-group r
// processes rows start+r, start+r+4, ... Cross-group combine in shared
// memory, then thread f writes the 4 stats for feature f.
// ---------------------------------------------------------------------------
__global__ void __launch_bounds__(128, 12)
seg_pool_kernel(const float* __restrict__ x, float* __restrict__ out, int G) {
    const int g = blockIdx.x;
    const int start = g_offsets[g];
    const int end   = g_offsets[g + 1];

    const int lane = threadIdx.x & 31;
    const int grp  = threadIdx.x >> 5;

    float4 s  = make_float4(0.f, 0.f, 0.f, 0.f);
    float4 q  = make_float4(0.f, 0.f, 0.f, 0.f);
    float4 mx = make_float4(-CUDART_INF_F, -CUDART_INF_F, -CUDART_INF_F, -CUDART_INF_F);
    float4 mn = make_float4( CUDART_INF_F,  CUDART_INF_F,  CUDART_INF_F,  CUDART_INF_F);

    const float4* __restrict__ xv = (const float4*)x;  // row stride = 32 float4

    #pragma unroll 4
    for (int r = start + grp; r < end; r += 4) {
        float4 v = __ldcs(&xv[(size_t)r * 32 + lane]);
        s.x += v.x; s.y += v.y; s.z += v.z; s.w += v.w;
        q.x = fmaf(v.x, v.x, q.x); q.y = fmaf(v.y, v.y, q.y);
        q.z = fmaf(v.z, v.z, q.z); q.w = fmaf(v.w, v.w, q.w);
        mx.x = fmaxf(mx.x, v.x); mx.y = fmaxf(mx.y, v.y);
        mx.z = fmaxf(mx.z, v.z); mx.w = fmaxf(mx.w, v.w);
        mn.x = fminf(mn.x, v.x); mn.y = fminf(mn.y, v.y);
        mn.z = fminf(mn.z, v.z); mn.w = fminf(mn.w, v.w);
    }

    // partials: [stat][group][lane] as float4 -> 4*4*32*16B = 8 KB
    __shared__ float4 sm4[4][4][32];
    sm4[0][grp][lane] = s;
    sm4[1][grp][lane] = q;
    sm4[2][grp][lane] = mx;
    sm4[3][grp][lane] = mn;
    __syncthreads();

    // thread f in [0,128) combines the 4 group partials for feature f
    const int f = threadIdx.x;
    float sum = 0.f, sq = 0.f;
    float M = -CUDART_INF_F, m = CUDART_INF_F;
    #pragma unroll
    for (int k = 0; k < 4; k++) {
        const float* p0 = (const float*)&sm4[0][k][0];
        const float* p1 = (const float*)&sm4[1][k][0];
        const float* p2 = (const float*)&sm4[2][k][0];
        const float* p3 = (const float*)&sm4[3][k][0];
        sum += p0[f];
        sq  += p1[f];
        M = fmaxf(M, p2[f]);
        m = fminf(m, p3[f]);
    }

    const float cnt  = (float)(end - start);
    const float mean = sum / cnt;
    const float var  = (sq - cnt * mean * mean) / (cnt - 1.0f);
    const float sd   = sqrtf(fmaxf(var, 0.0f));

    float* o = out + (size_t)g * 512;  // [4][128] per segment
    o[f]        = M;
    o[128 + f]  = m;
    o[256 + f]  = mean;
    o[384 + f]  = sd;
}

extern "C" void kernel_launch(void* const* d_in, const int* in_sizes, int n_in,
                              void* d_out, int out_size) {
    const float* x   = (const float*)d_in[0];
    const void*  seg = d_in[1];
    float* out = (float*)d_out;

    const int D = 128;
    const int n = in_sizes[0] / D;          // number of rows
    const int G = out_size / (4 * D);       // number of segments

    int tb = 256;
    int nb = (n + tb - 1) / tb;
    seg_boundaries_kernel<<<nb, tb>>>(seg, n, G);
    seg_pool_kernel<<<G, 128>>>(x, out, G);
}

// round 5
// speedup vs baseline: 1.1594x; 1.0463x over previous
#include <cuda_runtime.h>
#include <math_constants.h>

// Scratch for segment offsets (allocation-free rule: __device__ global).
__device__ int g_offsets[65537];

// ---------------------------------------------------------------------------
// Kernel 1: streaming boundary scan over the SORTED segment_ids array.
// Thread i reads seg[i]; successor comes from the neighbor lane via shfl
// (lane 31 does one extra scalar load). At each transition id -> next the
// thread fills g_offsets for every segment in (id, next]. After its writes,
// each CTA triggers the programmatic launch of the dependent pool kernel.
// Handles int64 (reference dtype) and int32 (JAX default) via a sniff.
// ---------------------------------------------------------------------------
__global__ void seg_boundaries_kernel(const void* __restrict__ seg, int n, int G) {
    const int i    = blockIdx.x * blockDim.x + threadIdx.x;
    const int lane = threadIdx.x & 31;

    // dtype sniff (warp-uniform): int64 word at index n/4 covers int32
    // elements n/2, n/2+1. Sorted ids: middle element ~G/2 != 0, so int32
    // data read as int64 is >= 2^32; genuine int64 data stays a small id.
    const long long probe = ((const long long*)seg)[n >> 2];
    const bool is64 = (probe >= 0) && (probe < (1LL << 31));

    const bool valid = (i < n);
    int id = 0;
    if (valid) {
        id = is64 ? (int)((const long long*)seg)[i] : ((const int*)seg)[i];
    }

    // successor: from right neighbor lane, else one scalar load / sentinel G
    const int from_shfl = __shfl_down_sync(0xffffffffu, id, 1);
    int next = G;
    if (valid && (i + 1 < n)) {
        if (lane < 31) next = from_shfl;
        else next = is64 ? (int)((const long long*)seg)[i + 1]
                         : ((const int*)seg)[i + 1];
    }

    if (valid) {
        if (i == 0) {
            for (int g = 0; g <= id; g++) g_offsets[g] = 0;
        }
        // first row of every segment in (id, next] is i+1 (no-op if id==next)
        for (int g = id + 1; g <= next; g++) g_offsets[g] = i + 1;
    }

    // Writes above are now issued; allow the dependent grid to launch.
    asm volatile("griddepcontrol.launch_dependents;");
}

// ---------------------------------------------------------------------------
// Kernel 2 (measured-best R2 loop, + PDL wait): one block per segment.
// 128 threads = 4 row-groups x 32 lanes. Lane l owns features [4l, 4l+4)
// via float4 (coalesced LDG.128, streaming hint). Row-group r processes rows
// start+r, start+r+4, ... Cross-group combine in shared memory, then thread
// f writes the 4 stats for feature f.
// ---------------------------------------------------------------------------
__global__ void __launch_bounds__(128, 12)
seg_pool_kernel(const float* __restrict__ x, float* __restrict__ out, int G) {
    // Block until the boundary kernel's g_offsets writes are visible.
    asm volatile("griddepcontrol.wait;");

    const int g = blockIdx.x;
    const int start = g_offsets[g];
    const int end   = g_offsets[g + 1];

    const int lane = threadIdx.x & 31;
    const int grp  = threadIdx.x >> 5;

    float4 s  = make_float4(0.f, 0.f, 0.f, 0.f);
    float4 q  = make_float4(0.f, 0.f, 0.f, 0.f);
    float4 mx = make_float4(-CUDART_INF_F, -CUDART_INF_F, -CUDART_INF_F, -CUDART_INF_F);
    float4 mn = make_float4( CUDART_INF_F,  CUDART_INF_F,  CUDART_INF_F,  CUDART_INF_F);

    const float4* __restrict__ xv = (const float4*)x;  // row stride = 32 float4

    #pragma unroll 4
    for (int r = start + grp; r < end; r += 4) {
        float4 v = __ldcs(&xv[(size_t)r * 32 + lane]);
        s.x += v.x; s.y += v.y; s.z += v.z; s.w += v.w;
        q.x = fmaf(v.x, v.x, q.x); q.y = fmaf(v.y, v.y, q.y);
        q.z = fmaf(v.z, v.z, q.z); q.w = fmaf(v.w, v.w, q.w);
        mx.x = fmaxf(mx.x, v.x); mx.y = fmaxf(mx.y, v.y);
        mx.z = fmaxf(mx.z, v.z); mx.w = fmaxf(mx.w, v.w);
        mn.x = fminf(mn.x, v.x); mn.y = fminf(mn.y, v.y);
        mn.z = fminf(mn.z, v.z); mn.w = fminf(mn.w, v.w);
    }

    // partials: [stat][group][lane] as float4 -> 4*4*32*16B = 8 KB
    __shared__ float4 sm4[4][4][32];
    sm4[0][grp][lane] = s;
    sm4[1][grp][lane] = q;
    sm4[2][grp][lane] = mx;
    sm4[3][grp][lane] = mn;
    __syncthreads();

    // thread f in [0,128) combines the 4 group partials for feature f
    const int f = threadIdx.x;
    float sum = 0.f, sq = 0.f;
    float M = -CUDART_INF_F, m = CUDART_INF_F;
    #pragma unroll
    for (int k = 0; k < 4; k++) {
        const float* p0 = (const float*)&sm4[0][k][0];
        const float* p1 = (const float*)&sm4[1][k][0];
        const float* p2 = (const float*)&sm4[2][k][0];
        const float* p3 = (const float*)&sm4[3][k][0];
        sum += p0[f];
        sq  += p1[f];
        M = fmaxf(M, p2[f]);
        m = fminf(m, p3[f]);
    }

    const float cnt  = (float)(end - start);
    const float mean = sum / cnt;
    const float var  = (sq - cnt * mean * mean) / (cnt - 1.0f);
    const float sd   = sqrtf(fmaxf(var, 0.0f));

    float* o = out + (size_t)g * 512;  // [4][128] per segment
    o[f]        = M;
    o[128 + f]  = m;
    o[256 + f]  = mean;
    o[384 + f]  = sd;
}

extern "C" void kernel_launch(void* const* d_in, const int* in_sizes, int n_in,
                              void* d_out, int out_size) {
    const float* x   = (const float*)d_in[0];
    const void*  seg = d_in[1];
    float* out = (float*)d_out;

    const int D = 128;
    const int n = in_sizes[0] / D;          // number of rows
    const int G = out_size / (4 * D);       // number of segments

    int tb = 256;
    int nb = (n + tb - 1) / tb;
    seg_boundaries_kernel<<<nb, tb>>>(seg, n, G);

    // Pool kernel with Programmatic Dependent Launch: its grid setup overlaps
    // the boundary kernel; CTAs wait on griddepcontrol.wait for g_offsets.
    cudaLaunchAttribute attrs[1];
    attrs[0].id = cudaLaunchAttributeProgrammaticStreamSerialization;
    attrs[0].val.programmaticStreamSerializationAllowed = 1;

    cudaLaunchConfig_t cfg = {};
    cfg.gridDim  = dim3((unsigned)G, 1, 1);
    cfg.blockDim = dim3(128, 1, 1);
    cfg.dynamicSmemBytes = 0;
    cfg.stream = 0;
    cfg.attrs = attrs;
    cfg.numAttrs = 1;

    cudaLaunchKernelEx(&cfg, seg_pool_kernel, x, out, G);
}

// round 6
// speedup vs baseline: 1.1909x; 1.0272x over previous
#include <cuda_runtime.h>
#include <math_constants.h>

// Scratch for segment offsets (allocation-free rule: __device__ global).
__device__ int g_offsets[65537];

// ---------------------------------------------------------------------------
// Kernel 1: vectorized streaming boundary scan over the SORTED segment_ids.
// Each thread owns 4 consecutive ids (one int4 / two longlong2 loads) plus a
// single scalar successor probe; interior transitions resolve in registers.
// At each transition id -> next the thread fills g_offsets for every segment
// in (id, next]. Thread of element 0 fills the head; the last element fills
// the tail up to G. Handles int64 (reference dtype) and int32 (JAX default)
// via an on-device dtype sniff.
// ---------------------------------------------------------------------------
__global__ void seg_boundaries_kernel(const void* __restrict__ seg, int n, int G) {
    const int base = (blockIdx.x * blockDim.x + threadIdx.x) * 4;
    if (base >= n) return;

    // dtype sniff (warp-uniform): int64 word at index n/4 covers int32
    // elements n/2, n/2+1. Sorted ids: middle element ~G/2 != 0, so int32
    // data read as int64 is >= 2^32; genuine int64 data stays a small id.
    const long long probe = ((const long long*)seg)[n >> 2];
    const bool is64 = (probe >= 0) && (probe < (1LL << 31));

    int v[5];  // 4 owned ids + successor (sentinel G past the end)
    if (base + 4 <= n) {
        if (is64) {
            const longlong2* p = (const longlong2*)((const long long*)seg + base);
            longlong2 a = __ldg(&p[0]);
            longlong2 b = __ldg(&p[1]);
            v[0] = (int)a.x; v[1] = (int)a.y; v[2] = (int)b.x; v[3] = (int)b.y;
        } else {
            int4 a = __ldg((const int4*)((const int*)seg + base));
            v[0] = a.x; v[1] = a.y; v[2] = a.z; v[3] = a.w;
        }
        v[4] = (base + 4 < n)
                 ? (is64 ? (int)((const long long*)seg)[base + 4]
                         : ((const int*)seg)[base + 4])
                 : G;
    } else {
        // ragged tail: scalar loads, pad with sentinel G
        #pragma unroll
        for (int j = 0; j < 5; j++) {
            const int idx = base + j;
            v[j] = (idx < n)
                     ? (is64 ? (int)((const long long*)seg)[idx]
                             : ((const int*)seg)[idx])
                     : G;
        }
    }

    if (base == 0) {
        for (int g = 0; g <= v[0]; g++) g_offsets[g] = 0;
    }
    #pragma unroll
    for (int j = 0; j < 4; j++) {
        // first row of every segment in (v[j], v[j+1]] is base+j+1
        for (int g = v[j] + 1; g <= v[j + 1]; g++) g_offsets[g] = base + j + 1;
    }
}

// ---------------------------------------------------------------------------
// Kernel 2 (measured-best R2 loop, unchanged): one block per segment.
// 128 threads = 4 row-groups x 32 lanes. Lane l owns features [4l, 4l+4)
// via float4 (coalesced LDG.128, streaming hint). Row-group r processes rows
// start+r, start+r+4, ... Cross-group combine in shared memory, then thread
// f writes the 4 stats for feature f.
// ---------------------------------------------------------------------------
__global__ void __launch_bounds__(128, 12)
seg_pool_kernel(const float* __restrict__ x, float* __restrict__ out, int G) {
    const int g = blockIdx.x;
    const int start = g_offsets[g];
    const int end   = g_offsets[g + 1];

    const int lane = threadIdx.x & 31;
    const int grp  = threadIdx.x >> 5;

    float4 s  = make_float4(0.f, 0.f, 0.f, 0.f);
    float4 q  = make_float4(0.f, 0.f, 0.f, 0.f);
    float4 mx = make_float4(-CUDART_INF_F, -CUDART_INF_F, -CUDART_INF_F, -CUDART_INF_F);
    float4 mn = make_float4( CUDART_INF_F,  CUDART_INF_F,  CUDART_INF_F,  CUDART_INF_F);

    const float4* __restrict__ xv = (const float4*)x;  // row stride = 32 float4

    #pragma unroll 4
    for (int r = start + grp; r < end; r += 4) {
        float4 v = __ldcs(&xv[(size_t)r * 32 + lane]);
        s.x += v.x; s.y += v.y; s.z += v.z; s.w += v.w;
        q.x = fmaf(v.x, v.x, q.x); q.y = fmaf(v.y, v.y, q.y);
        q.z = fmaf(v.z, v.z, q.z); q.w = fmaf(v.w, v.w, q.w);
        mx.x = fmaxf(mx.x, v.x); mx.y = fmaxf(mx.y, v.y);
        mx.z = fmaxf(mx.z, v.z); mx.w = fmaxf(mx.w, v.w);
        mn.x = fminf(mn.x, v.x); mn.y = fminf(mn.y, v.y);
        mn.z = fminf(mn.z, v.z); mn.w = fminf(mn.w, v.w);
    }

    // partials: [stat][group][lane] as float4 -> 4*4*32*16B = 8 KB
    __shared__ float4 sm4[4][4][32];
    sm4[0][grp][lane] = s;
    sm4[1][grp][lane] = q;
    sm4[2][grp][lane] = mx;
    sm4[3][grp][lane] = mn;
    __syncthreads();

    // thread f in [0,128) combines the 4 group partials for feature f
    const int f = threadIdx.x;
    float sum = 0.f, sq = 0.f;
    float M = -CUDART_INF_F, m = CUDART_INF_F;
    #pragma unroll
    for (int k = 0; k < 4; k++) {
        const float* p0 = (const float*)&sm4[0][k][0];
        const float* p1 = (const float*)&sm4[1][k][0];
        const float* p2 = (const float*)&sm4[2][k][0];
        const float* p3 = (const float*)&sm4[3][k][0];
        sum += p0[f];
        sq  += p1[f];
        M = fmaxf(M, p2[f]);
        m = fminf(m, p3[f]);
    }

    const float cnt  = (float)(end - start);
    const float mean = sum / cnt;
    const float var  = (sq - cnt * mean * mean) / (cnt - 1.0f);
    const float sd   = sqrtf(fmaxf(var, 0.0f));

    float* o = out + (size_t)g * 512;  // [4][128] per segment
    o[f]        = M;
    o[128 + f]  = m;
    o[256 + f]  = mean;
    o[384 + f]  = sd;
}

extern "C" void kernel_launch(void* const* d_in, const int* in_sizes, int n_in,
                              void* d_out, int out_size) {
    const float* x   = (const float*)d_in[0];
    const void*  seg = d_in[1];
    float* out = (float*)d_out;

    const int D = 128;
    const int n = in_sizes[0] / D;          // number of rows
    const int G = out_size / (4 * D);       // number of segments

    const int elems_per_thread = 4;
    const int tb = 256;
    const int work = (n + elems_per_thread - 1) / elems_per_thread;
    const int nb = (work + tb - 1) / tb;
    seg_boundaries_kernel<<<nb, tb>>>(seg, n, G);
    seg_pool_kernel<<<G, 128>>>(x, out, G);
}